// round 2
// baseline (speedup 1.0000x reference)
#include <cuda_runtime.h>
#include <math.h>

#define NN 8192
#define CC 512
#define KK 64
#define PHI_ROWS 128
#define PHI_NBLK (NN/PHI_ROWS)     // 64 blocks per matrix
#define FILL_BLKS 1024
#define GEMM_NBLK (NN/64)          // 128 row-blocks of 64 for gemm

typedef unsigned long long ull;

// Scratch (device globals — no allocation allowed)
__device__ float g_phi_i[NN*KK];
__device__ float g_phi_j[NN*KK];
__device__ float g_At[CC*KK];      // [c][k] = 1/s^2
__device__ float g_Bt[CC*KK];      // [c][k] = m/s^2
__device__ float g_t3[KK];         // sum_c m^2/s^2
__device__ int   g_nz[2][PHI_NBLK];// per-128-row-block nonzero flags

#define FMA2(d,a,b,c) asm("fma.rn.f32x2 %0, %1, %2, %3;" : "=l"(d) : "l"(a), "l"(b), "l"(c))

__device__ __forceinline__ ull pack2(float lo, float hi) {
    ull r; asm("mov.b64 %0, {%1, %2};" : "=l"(r) : "f"(lo), "f"(hi)); return r;
}
__device__ __forceinline__ void unpack2(ull v, float& lo, float& hi) {
    asm("mov.b64 {%0, %1}, %2;" : "=f"(lo), "=f"(hi) : "l"(v));
}

// ---------------------------------------------------------------------------
// Prep: A = 1/s^2, B = m/s^2 (transposed to [c][k]), t3[k] = sum_c m^2/s^2
// 64 blocks (one per k) x 512 threads (one per c).
// ---------------------------------------------------------------------------
__global__ __launch_bounds__(512)
void prep_kernel(const float* __restrict__ means,
                 const float* __restrict__ scales) {
    const int k = blockIdx.x;
    const int t = threadIdx.x;
    float s   = scales[k*CC + t];
    float m   = means [k*CC + t];
    float is2 = 1.0f / (s * s);
    g_At[t*KK + k] = is2;
    g_Bt[t*KK + k] = m * is2;
    float v = m * m * is2;
    // warp reduce
    #pragma unroll
    for (int o = 16; o > 0; o >>= 1)
        v += __shfl_down_sync(0xffffffffu, v, o);
    __shared__ float red[16];
    if ((t & 31) == 0) red[t >> 5] = v;
    __syncthreads();
    if (t < 16) {
        float x = red[t];
        #pragma unroll
        for (int o = 8; o > 0; o >>= 1)
            x += __shfl_down_sync(0xffffu, x, o);
        if (t == 0) g_t3[k] = x;
    }
}

// ---------------------------------------------------------------------------
// Fused phi + zero-fill.
//   Blocks [0,128): phi. Block covers 128 rows x 64 k. 256 threads,
//     per-thread 4n x 8k micro-tile, packed f32x2 FMAs (acc packed over k).
//     f and f^2 stored DUPLICATED in smem so ulonglong2 LDS yields packed
//     operands with zero pack instructions.
//   Blocks [128, 128+FILL_BLKS): write zeros over the whole 256MB output.
// ---------------------------------------------------------------------------
__global__ __launch_bounds__(256)
void phi_fill_kernel(const float* __restrict__ f_i,
                     const float* __restrict__ f_j,
                     const float* __restrict__ weights,
                     float* __restrict__ out) {
    const int bid = blockIdx.x;
    const int t   = threadIdx.x;

    if (bid >= 2*PHI_NBLK) {
        // ---- fill role ----
        float4 z = make_float4(0.f, 0.f, 0.f, 0.f);
        float4* o4 = (float4*)out;
        const size_t total4 = (size_t)NN * NN / 4;   // 16M float4
        size_t idx = (size_t)(bid - 2*PHI_NBLK) * 256 + t;
        const size_t stride = (size_t)FILL_BLKS * 256;
        for (size_t p = idx; p < total4; p += stride)
            o4[p] = z;
        return;
    }

    // ---- phi role ----
    const int mat = bid >> 6;            // 0: f_i, 1: f_j
    const int blk = bid & 63;
    const float* __restrict__ f = mat ? f_j : f_i;
    float* __restrict__ phi = mat ? g_phi_j : g_phi_i;
    const int n0 = blk * PHI_ROWS;

    __shared__ float fsd [16][264];      // duplicated: fsd[c][2n]=fsd[c][2n+1]=f
    __shared__ float f2sd[16][264];
    __shared__ float As  [16][72];
    __shared__ float Bs  [16][72];

    const int kg = t & 7;                // 8 k-groups
    const int ng = t >> 3;               // 32 n-groups
    const int kx = kg * 8;
    const int ny = ng * 4;

    ull acc1[4][4], acc2[4][4];          // [i][jp], packed pairs over k
    #pragma unroll
    for (int i = 0; i < 4; i++)
        #pragma unroll
        for (int j = 0; j < 4; j++) { acc1[i][j] = 0ull; acc2[i][j] = 0ull; }

    for (int cc = 0; cc < CC; cc += 16) {
        // load f chunk [128 rows x 16 c], duplicated + squared
        #pragma unroll
        for (int v = 0; v < 2; v++) {
            int vid = t + v * 256;       // 512 float4 slots
            int row = vid >> 2;          // 4 float4 per row
            int c4  = (vid & 3) * 4;
            float4 x = *(const float4*)(f + (size_t)(n0 + row) * CC + cc + c4);
            int r2 = 2 * row;
            *(float2*)&fsd [c4+0][r2] = make_float2(x.x, x.x);
            *(float2*)&fsd [c4+1][r2] = make_float2(x.y, x.y);
            *(float2*)&fsd [c4+2][r2] = make_float2(x.z, x.z);
            *(float2*)&fsd [c4+3][r2] = make_float2(x.w, x.w);
            *(float2*)&f2sd[c4+0][r2] = make_float2(x.x*x.x, x.x*x.x);
            *(float2*)&f2sd[c4+1][r2] = make_float2(x.y*x.y, x.y*x.y);
            *(float2*)&f2sd[c4+2][r2] = make_float2(x.z*x.z, x.z*x.z);
            *(float2*)&f2sd[c4+3][r2] = make_float2(x.w*x.w, x.w*x.w);
        }
        // load A/B chunk [16 c x 64 k]
        {
            int c  = t >> 4;
            int k4 = (t & 15) * 4;
            *(float4*)&As[c][k4] = *(const float4*)(g_At + (size_t)(cc + c) * KK + k4);
            *(float4*)&Bs[c][k4] = *(const float4*)(g_Bt + (size_t)(cc + c) * KK + k4);
        }
        __syncthreads();

        #pragma unroll 4
        for (int c = 0; c < 16; c++) {
            ulonglong2 fpa = *(const ulonglong2*)&fsd [c][2*ny];
            ulonglong2 fpb = *(const ulonglong2*)&fsd [c][2*ny + 4];
            ulonglong2 qpa = *(const ulonglong2*)&f2sd[c][2*ny];
            ulonglong2 qpb = *(const ulonglong2*)&f2sd[c][2*ny + 4];
            ulonglong2 apa = *(const ulonglong2*)&As  [c][kx];
            ulonglong2 apb = *(const ulonglong2*)&As  [c][kx + 4];
            ulonglong2 bpa = *(const ulonglong2*)&Bs  [c][kx];
            ulonglong2 bpb = *(const ulonglong2*)&Bs  [c][kx + 4];
            ull fp[4] = {fpa.x, fpa.y, fpb.x, fpb.y};
            ull qp[4] = {qpa.x, qpa.y, qpb.x, qpb.y};
            ull ap[4] = {apa.x, apa.y, apb.x, apb.y};
            ull bp[4] = {bpa.x, bpa.y, bpb.x, bpb.y};
            #pragma unroll
            for (int i = 0; i < 4; i++)
                #pragma unroll
                for (int jp = 0; jp < 4; jp++) {
                    FMA2(acc1[i][jp], qp[i], ap[jp], acc1[i][jp]);
                    FMA2(acc2[i][jp], fp[i], bp[jp], acc2[i][jp]);
                }
        }
        __syncthreads();
    }

    // epilogue: d = -(acc1 - 2*acc2 + t3);  phi = exp(d) (* w for mat 0)
    ull nt3p[4];
    #pragma unroll
    for (int jp = 0; jp < 4; jp++)
        nt3p[jp] = pack2(-g_t3[kx + 2*jp], -g_t3[kx + 2*jp + 1]);
    const ull m2 = pack2(-2.0f, -2.0f);
    const ull m1 = pack2(-1.0f, -1.0f);

    float wv[8];
    #pragma unroll
    for (int j = 0; j < 8; j++)
        wv[j] = (mat == 0) ? weights[kx + j] : 1.0f;

    int lnz = 0;
    #pragma unroll
    for (int i = 0; i < 4; i++) {
        float p[8];
        #pragma unroll
        for (int jp = 0; jp < 4; jp++) {
            ull s, d;
            FMA2(s, acc2[i][jp], m2, acc1[i][jp]);   // acc1 - 2*acc2
            FMA2(d, s, m1, nt3p[jp]);                // -(acc1 - 2*acc2 + t3)
            float d0, d1; unpack2(d, d0, d1);
            p[2*jp]   = expf(d0) * wv[2*jp];
            p[2*jp+1] = expf(d1) * wv[2*jp+1];
            lnz |= (p[2*jp] != 0.0f) | (p[2*jp+1] != 0.0f);
        }
        size_t base = (size_t)(n0 + ny + i) * KK + kx;
        *(float4*)(phi + base)     = make_float4(p[0], p[1], p[2], p[3]);
        *(float4*)(phi + base + 4) = make_float4(p[4], p[5], p[6], p[7]);
    }
    int any = __syncthreads_or(lnz);
    if (t == 0) g_nz[mat][blk] = any;
}

// ---------------------------------------------------------------------------
// GEMM over nonzero tiles only. Fill already wrote zeros everywhere, so
// zero tiles need no work. Grid = 128 row-blocks (64 rows each); blocks
// whose phi_i row-block is all-zero exit after one load. Nonzero rows loop
// over the 128 column blocks, skipping zero phi_j blocks.
// ---------------------------------------------------------------------------
__global__ __launch_bounds__(256)
void gemm_kernel(float* __restrict__ out) {
    const int rb = blockIdx.x;                 // 64-row block of output
    if (g_nz[0][rb >> 1] == 0) return;

    const int t   = threadIdx.x;
    const int txm = (t & 15) * 4;              // local col base
    const int tyn = (t >> 4) * 4;              // local row base

    __shared__ float As[64][68];               // [k][n_local]  (phi_i rows)
    __shared__ float Bs[64][68];               // [k][m_local]  (phi_j rows)

    // load phi_i row tile once
    #pragma unroll
    for (int v = 0; v < 4; v++) {
        int vid = t + v * 256;
        int row = vid >> 4;
        int k4  = (vid & 15) * 4;
        float4 a = *(const float4*)(g_phi_i + (size_t)(rb * 64 + row) * KK + k4);
        As[k4+0][row] = a.x; As[k4+1][row] = a.y;
        As[k4+2][row] = a.z; As[k4+3][row] = a.w;
    }

    for (int cb = 0; cb < GEMM_NBLK; cb++) {
        if (g_nz[1][cb >> 1] == 0) continue;

        #pragma unroll
        for (int v = 0; v < 4; v++) {
            int vid = t + v * 256;
            int row = vid >> 4;
            int k4  = (vid & 15) * 4;
            float4 b = *(const float4*)(g_phi_j + (size_t)(cb * 64 + row) * KK + k4);
            Bs[k4+0][row] = b.x; Bs[k4+1][row] = b.y;
            Bs[k4+2][row] = b.z; Bs[k4+3][row] = b.w;
        }
        __syncthreads();

        float acc[4][4];
        #pragma unroll
        for (int i = 0; i < 4; i++)
            #pragma unroll
            for (int j = 0; j < 4; j++) acc[i][j] = 0.f;

        #pragma unroll 8
        for (int k = 0; k < 64; k++) {
            float4 a4 = *(const float4*)&As[k][tyn];
            float4 b4 = *(const float4*)&Bs[k][txm];
            float av[4] = {a4.x, a4.y, a4.z, a4.w};
            float bv[4] = {b4.x, b4.y, b4.z, b4.w};
            #pragma unroll
            for (int i = 0; i < 4; i++)
                #pragma unroll
                for (int j = 0; j < 4; j++)
                    acc[i][j] = fmaf(av[i], bv[j], acc[i][j]);
        }

        #pragma unroll
        for (int i = 0; i < 4; i++) {
            size_t row = (size_t)(rb * 64 + tyn + i);
            *(float4*)(out + row * NN + cb * 64 + txm) =
                make_float4(acc[i][0], acc[i][1], acc[i][2], acc[i][3]);
        }
        __syncthreads();
    }
}

// ---------------------------------------------------------------------------
extern "C" void kernel_launch(void* const* d_in, const int* in_sizes, int n_in,
                              void* d_out, int out_size) {
    const float* f_i     = (const float*)d_in[0];
    const float* f_j     = (const float*)d_in[1];
    const float* means   = (const float*)d_in[2];
    const float* scales  = (const float*)d_in[3];
    const float* weights = (const float*)d_in[4];
    float* out = (float*)d_out;

    prep_kernel<<<KK, 512>>>(means, scales);
    phi_fill_kernel<<<2*PHI_NBLK + FILL_BLKS, 256>>>(f_i, f_j, weights, out);
    gemm_kernel<<<GEMM_NBLK, 256>>>(out);
}

// round 3
// speedup vs baseline: 1.0134x; 1.0134x over previous
#include <cuda_runtime.h>
#include <math.h>

#define NN 8192
#define CC 512
#define KK 64
#define NBLK (NN/64)   // 128 row-blocks of 64

typedef unsigned long long ull;

// Scratch (device globals — no allocation allowed)
__device__ float g_phi_i[NN*KK];
__device__ float g_phi_j[NN*KK];
__device__ float g_At[CC*KK];   // [c][k] = 1/s^2
__device__ float g_Bt[CC*KK];   // [c][k] = m/s^2
__device__ float g_t3[KK];      // sum_c m^2/s^2
__device__ int   g_nz[2][NBLK]; // per-64-row-block nonzero flags

#define FMA2(d,a,b,c) asm("fma.rn.f32x2 %0, %1, %2, %3;" : "=l"(d) : "l"(a), "l"(b), "l"(c))

__device__ __forceinline__ ull pack2(float lo, float hi) {
    ull r; asm("mov.b64 %0, {%1, %2};" : "=l"(r) : "f"(lo), "f"(hi)); return r;
}
__device__ __forceinline__ void unpack2(ull v, float& lo, float& hi) {
    asm("mov.b64 {%0, %1}, %2;" : "=f"(lo), "=f"(hi) : "l"(v));
}

// ---------------------------------------------------------------------------
// Prep: A = 1/s^2, B = m/s^2 (transposed to [c][k]), t3[k] = sum_c m^2/s^2
// ---------------------------------------------------------------------------
__global__ __launch_bounds__(512)
void prep_kernel(const float* __restrict__ means,
                 const float* __restrict__ scales) {
    const int k = blockIdx.x;
    const int t = threadIdx.x;
    float s   = scales[k*CC + t];
    float m   = means [k*CC + t];
    float is2 = 1.0f / (s * s);
    g_At[t*KK + k] = is2;
    g_Bt[t*KK + k] = m * is2;
    float v = m * m * is2;
    #pragma unroll
    for (int o = 16; o > 0; o >>= 1)
        v += __shfl_down_sync(0xffffffffu, v, o);
    __shared__ float red[16];
    if ((t & 31) == 0) red[t >> 5] = v;
    __syncthreads();
    if (t < 16) {
        float x = red[t];
        #pragma unroll
        for (int o = 8; o > 0; o >>= 1)
            x += __shfl_down_sync(0xffffu, x, o);
        if (t == 0) g_t3[k] = x;
    }
}

// ---------------------------------------------------------------------------
// Phi with packed f32x2 FMAs. 64 rows x 64 k per block, 256 threads,
// 4n x 4k micro-tile, accumulators packed over k (2 lanes = 2 adjacent k).
// f and f^2 stored DUPLICATED in smem so a 64-bit LDS yields a ready packed
// (f,f) operand with zero pack instructions.
//   dist[n,k] = -( sum_c f^2*A[c,k] - 2*sum_c f*B[c,k] + t3[k] )
// ---------------------------------------------------------------------------
__global__ __launch_bounds__(256)
void phi_kernel(const float* __restrict__ f_i, const float* __restrict__ f_j,
                const float* __restrict__ weights) {
    const int isI = (blockIdx.y == 0);
    const float* __restrict__ f = isI ? f_i : f_j;
    float* __restrict__ phi = isI ? g_phi_j : g_phi_i; // fixed below
    phi = isI ? g_phi_i : g_phi_j;
    const int n0 = blockIdx.x * 64;

    __shared__ float fsd [16][136];   // duplicated: fsd[c][2n]=fsd[c][2n+1]=f
    __shared__ float f2sd[16][136];
    __shared__ float As  [16][68];    // [c][k] = 1/s^2
    __shared__ float Bs  [16][68];    // [c][k] = m/s^2

    const int kg = threadIdx.x & 15;  // 16 k-groups of 4
    const int ng = threadIdx.x >> 4;  // 16 n-groups of 4
    const int kx = kg * 4;
    const int ny = ng * 4;
    const int t  = threadIdx.x;

    ull acc1[4][2], acc2[4][2];       // [n][kp] packed pairs over k
    #pragma unroll
    for (int i = 0; i < 4; i++) {
        acc1[i][0] = 0ull; acc1[i][1] = 0ull;
        acc2[i][0] = 0ull; acc2[i][1] = 0ull;
    }

    for (int cc = 0; cc < CC; cc += 16) {
        // load f chunk [64 rows x 16 c] duplicated + squared: 256 float4, 1/thread
        {
            int row = t >> 2;           // 4 float4 per row
            int c4  = (t & 3) * 4;
            float4 x = *(const float4*)(f + (size_t)(n0 + row) * CC + cc + c4);
            int r2 = 2 * row;
            *(float2*)&fsd [c4+0][r2] = make_float2(x.x, x.x);
            *(float2*)&fsd [c4+1][r2] = make_float2(x.y, x.y);
            *(float2*)&fsd [c4+2][r2] = make_float2(x.z, x.z);
            *(float2*)&fsd [c4+3][r2] = make_float2(x.w, x.w);
            *(float2*)&f2sd[c4+0][r2] = make_float2(x.x*x.x, x.x*x.x);
            *(float2*)&f2sd[c4+1][r2] = make_float2(x.y*x.y, x.y*x.y);
            *(float2*)&f2sd[c4+2][r2] = make_float2(x.z*x.z, x.z*x.z);
            *(float2*)&f2sd[c4+3][r2] = make_float2(x.w*x.w, x.w*x.w);
        }
        // load A/B chunk [16 c x 64 k]: 256 float4 each, 1/thread
        {
            int c  = t >> 4;
            int k4 = (t & 15) * 4;
            *(float4*)&As[c][k4] = *(const float4*)(g_At + (size_t)(cc + c) * KK + k4);
            *(float4*)&Bs[c][k4] = *(const float4*)(g_Bt + (size_t)(cc + c) * KK + k4);
        }
        __syncthreads();

        #pragma unroll 4
        for (int c = 0; c < 16; c++) {
            // packed (f,f) and (f2,f2) for 4 n  (2 x 128-bit LDS each)
            ulonglong2 fa = *(const ulonglong2*)&fsd [c][2*ny];
            ulonglong2 fb = *(const ulonglong2*)&fsd [c][2*ny + 4];
            ulonglong2 qa = *(const ulonglong2*)&f2sd[c][2*ny];
            ulonglong2 qb = *(const ulonglong2*)&f2sd[c][2*ny + 4];
            // packed (A_k,A_k+1) pairs for 4 k (1 x 128-bit LDS each)
            ulonglong2 ap = *(const ulonglong2*)&As[c][kx];
            ulonglong2 bp = *(const ulonglong2*)&Bs[c][kx];
            ull fp[4] = {fa.x, fa.y, fb.x, fb.y};
            ull qp[4] = {qa.x, qa.y, qb.x, qb.y};
            #pragma unroll
            for (int i = 0; i < 4; i++) {
                FMA2(acc1[i][0], qp[i], ap.x, acc1[i][0]);
                FMA2(acc1[i][1], qp[i], ap.y, acc1[i][1]);
                FMA2(acc2[i][0], fp[i], bp.x, acc2[i][0]);
                FMA2(acc2[i][1], fp[i], bp.y, acc2[i][1]);
            }
        }
        __syncthreads();
    }

    // epilogue: d = -(acc1 - 2*acc2 + t3);  phi = exp(d) (* w for i-side)
    ull nt3p[2];
    nt3p[0] = pack2(-g_t3[kx],     -g_t3[kx + 1]);
    nt3p[1] = pack2(-g_t3[kx + 2], -g_t3[kx + 3]);
    const ull m2 = pack2(-2.0f, -2.0f);
    const ull m1 = pack2(-1.0f, -1.0f);

    float wv[4];
    #pragma unroll
    for (int j = 0; j < 4; j++)
        wv[j] = isI ? weights[kx + j] : 1.0f;

    int lnz = 0;
    #pragma unroll
    for (int i = 0; i < 4; i++) {
        float p[4];
        #pragma unroll
        for (int jp = 0; jp < 2; jp++) {
            ull s, d;
            FMA2(s, acc2[i][jp], m2, acc1[i][jp]);   // acc1 - 2*acc2
            FMA2(d, s, m1, nt3p[jp]);                // -(acc1 - 2*acc2 + t3)
            float d0, d1; unpack2(d, d0, d1);
            p[2*jp]   = expf(d0) * wv[2*jp];
            p[2*jp+1] = expf(d1) * wv[2*jp+1];
            lnz |= (p[2*jp] != 0.0f) | (p[2*jp+1] != 0.0f);
        }
        *(float4*)(phi + (size_t)(n0 + ny + i) * KK + kx) =
            make_float4(p[0], p[1], p[2], p[3]);
    }
    int any = __syncthreads_or(lnz);
    if (t == 0) g_nz[isI ? 0 : 1][blockIdx.x] = any;
}

// ---------------------------------------------------------------------------
// GEMM (R1-proven): out[n,m] = sum_k phi_i[n,k]*phi_j[m,k]. 64x64 tiles,
// 256 threads, 4x4 micro-tile. Zero tiles write zeros directly (exact).
// ---------------------------------------------------------------------------
__global__ __launch_bounds__(256)
void gemm_kernel(float* __restrict__ out) {
    const int bm = blockIdx.y;
    const int bn = blockIdx.x;
    const int t  = threadIdx.x;
    const int txm = (t & 15) * 4;
    const int tyn = (t >> 4) * 4;

    if (g_nz[0][bm] == 0 || g_nz[1][bn] == 0) {
        float4 z = make_float4(0.f, 0.f, 0.f, 0.f);
        #pragma unroll
        for (int i = 0; i < 4; i++) {
            size_t row = (size_t)(bm * 64 + tyn + i);
            *(float4*)(out + row * NN + bn * 64 + txm) = z;
        }
        return;
    }

    __shared__ float As[64][68];
    __shared__ float Bs[64][68];
    #pragma unroll
    for (int v = 0; v < 4; v++) {
        int vid = t + v * 256;
        int row = vid >> 4;
        int k4  = (vid & 15) * 4;
        float4 a = *(const float4*)(g_phi_i + (size_t)(bm * 64 + row) * KK + k4);
        As[k4+0][row] = a.x; As[k4+1][row] = a.y; As[k4+2][row] = a.z; As[k4+3][row] = a.w;
        float4 b = *(const float4*)(g_phi_j + (size_t)(bn * 64 + row) * KK + k4);
        Bs[k4+0][row] = b.x; Bs[k4+1][row] = b.y; Bs[k4+2][row] = b.z; Bs[k4+3][row] = b.w;
    }
    __syncthreads();

    float acc[4][4];
    #pragma unroll
    for (int i = 0; i < 4; i++)
        #pragma unroll
        for (int j = 0; j < 4; j++) acc[i][j] = 0.f;

    #pragma unroll 8
    for (int k = 0; k < 64; k++) {
        float4 a4 = *(const float4*)&As[k][tyn];
        float4 b4 = *(const float4*)&Bs[k][txm];
        float av[4] = {a4.x, a4.y, a4.z, a4.w};
        float bv[4] = {b4.x, b4.y, b4.z, b4.w};
        #pragma unroll
        for (int i = 0; i < 4; i++)
            #pragma unroll
            for (int j = 0; j < 4; j++)
                acc[i][j] = fmaf(av[i], bv[j], acc[i][j]);
    }

    #pragma unroll
    for (int i = 0; i < 4; i++) {
        size_t row = (size_t)(bm * 64 + tyn + i);
        *(float4*)(out + row * NN + bn * 64 + txm) =
            make_float4(acc[i][0], acc[i][1], acc[i][2], acc[i][3]);
    }
}

// ---------------------------------------------------------------------------
extern "C" void kernel_launch(void* const* d_in, const int* in_sizes, int n_in,
                              void* d_out, int out_size) {
    const float* f_i     = (const float*)d_in[0];
    const float* f_j     = (const float*)d_in[1];
    const float* means   = (const float*)d_in[2];
    const float* scales  = (const float*)d_in[3];
    const float* weights = (const float*)d_in[4];
    float* out = (float*)d_out;

    prep_kernel<<<KK, 512>>>(means, scales);
    phi_kernel<<<dim3(NBLK, 2), 256>>>(f_i, f_j, weights);
    gemm_kernel<<<dim3(NBLK, NBLK), 256>>>(out);
}

// round 4
// speedup vs baseline: 1.3781x; 1.3599x over previous
#include <cuda_runtime.h>
#include <math.h>

#define NN 8192
#define CC 512
#define KK 64
#define NBLK (NN/64)        // 128 row-blocks of 64 (gemm + flags)
#define PHI_ROWS 128
#define PHI_NBLK (NN/PHI_ROWS)

typedef unsigned long long ull;

// Scratch (device globals — no allocation allowed)
__device__ float g_phi_i[NN*KK];
__device__ float g_phi_j[NN*KK];
__device__ float g_At[CC*KK];   // [c][k] = 1/s^2
__device__ float g_Bt[CC*KK];   // [c][k] = -2*m/s^2
__device__ float g_t3[KK];      // sum_c m^2/s^2
__device__ int   g_nz[2][NBLK]; // per-64-row-block nonzero flags

#define FMA2(d,a,b,c) asm("fma.rn.f32x2 %0, %1, %2, %3;" : "=l"(d) : "l"(a), "l"(b), "l"(c))

__device__ __forceinline__ ull pack2(float lo, float hi) {
    ull r; asm("mov.b64 %0, {%1, %2};" : "=l"(r) : "f"(lo), "f"(hi)); return r;
}
__device__ __forceinline__ void unpack2(ull v, float& lo, float& hi) {
    asm("mov.b64 {%0, %1}, %2;" : "=f"(lo), "=f"(hi) : "l"(v));
}

// ---------------------------------------------------------------------------
// Prep: A = 1/s^2, B = -2*m/s^2 (transposed to [c][k]), t3[k] = sum_c m^2/s^2
// ---------------------------------------------------------------------------
__global__ __launch_bounds__(512)
void prep_kernel(const float* __restrict__ means,
                 const float* __restrict__ scales) {
    const int k = blockIdx.x;
    const int t = threadIdx.x;
    float s   = scales[k*CC + t];
    float m   = means [k*CC + t];
    float is2 = 1.0f / (s * s);
    g_At[t*KK + k] = is2;
    g_Bt[t*KK + k] = -2.0f * m * is2;
    float v = m * m * is2;
    #pragma unroll
    for (int o = 16; o > 0; o >>= 1)
        v += __shfl_down_sync(0xffffffffu, v, o);
    __shared__ float red[16];
    if ((t & 31) == 0) red[t >> 5] = v;
    __syncthreads();
    if (t < 16) {
        float x = red[t];
        #pragma unroll
        for (int o = 8; o > 0; o >>= 1)
            x += __shfl_down_sync(0xffffu, x, o);
        if (t == 0) g_t3[k] = x;
    }
}

// ---------------------------------------------------------------------------
// Phi, f32x2, accumulators packed over k. No smem duplication:
// A/B packed pairs come natural from smem; the (f,f) twin is built in regs.
// Algebra: f^2*a - 2*f*m*a = f*(f*a + b), b = -2m/s^2  (prep-folded).
// Block: 128 rows x 64 k, 256 threads, per-thread 8n x 4k (2 packed kp).
//   dist[n,k] = -( sum_c f*(f*A[c,k] + B[c,k]) + t3[k] );  phi = exp(dist)(*w)
// ---------------------------------------------------------------------------
__global__ __launch_bounds__(256)
void phi_kernel(const float* __restrict__ f_i, const float* __restrict__ f_j,
                const float* __restrict__ weights) {
    const int isI = (blockIdx.y == 0);
    const float* __restrict__ f = isI ? f_i : f_j;
    float* __restrict__ phi = isI ? g_phi_i : g_phi_j;
    const int n0 = blockIdx.x * PHI_ROWS;

    __shared__ float fs[16][132];   // [c_local][n_local], natural
    __shared__ float As[16][68];    // [c_local][k] = 1/s^2
    __shared__ float Bs[16][68];    // [c_local][k] = -2m/s^2

    const int t  = threadIdx.x;
    const int kg = t & 15;          // 16 k-groups of 4
    const int ng = t >> 4;          // 16 n-groups of 8
    const int kx = kg * 4;
    const int ny = ng * 8;

    ull acc[8][2];                  // [n][kp], each packs (k, k+1)
    #pragma unroll
    for (int i = 0; i < 8; i++) { acc[i][0] = 0ull; acc[i][1] = 0ull; }

    for (int cc = 0; cc < CC; cc += 16) {
        // f chunk [128 rows x 16 c] transposed: 512 float4, 2 per thread
        #pragma unroll
        for (int v = 0; v < 2; v++) {
            int vid = t + v * 256;
            int row = vid >> 2;             // 4 float4 per row
            int c4  = (vid & 3) * 4;
            float4 x = *(const float4*)(f + (size_t)(n0 + row) * CC + cc + c4);
            fs[c4+0][row] = x.x; fs[c4+1][row] = x.y;
            fs[c4+2][row] = x.z; fs[c4+3][row] = x.w;
        }
        // A/B chunk [16 c x 64 k]: 256 float4 each, 1 per thread
        {
            int c  = t >> 4;
            int k4 = (t & 15) * 4;
            *(float4*)&As[c][k4] = *(const float4*)(g_At + (size_t)(cc + c) * KK + k4);
            *(float4*)&Bs[c][k4] = *(const float4*)(g_Bt + (size_t)(cc + c) * KK + k4);
        }
        __syncthreads();

        #pragma unroll
        for (int c = 0; c < 16; c++) {
            ulonglong2 ap = *(const ulonglong2*)&As[c][kx];  // (a0,a1),(a2,a3)
            ulonglong2 bp = *(const ulonglong2*)&Bs[c][kx];
            float4 fa = *(const float4*)&fs[c][ny];
            float4 fb = *(const float4*)&fs[c][ny + 4];
            float fv[8] = {fa.x, fa.y, fa.z, fa.w, fb.x, fb.y, fb.z, fb.w};
            #pragma unroll
            for (int n = 0; n < 8; n++) {
                ull fd = pack2(fv[n], fv[n]);
                ull t0, t1;
                FMA2(t0, fd, ap.x, bp.x);            // f*a + b
                FMA2(acc[n][0], fd, t0, acc[n][0]);  // += f*(f*a+b)
                FMA2(t1, fd, ap.y, bp.y);
                FMA2(acc[n][1], fd, t1, acc[n][1]);
            }
        }
        __syncthreads();
    }

    // epilogue: d = -(acc + t3);  phi = exp(d) (* w for i-side)
    ull nt3[2];
    nt3[0] = pack2(-g_t3[kx],     -g_t3[kx + 1]);
    nt3[1] = pack2(-g_t3[kx + 2], -g_t3[kx + 3]);
    const ull m1 = pack2(-1.0f, -1.0f);

    float wv[4];
    #pragma unroll
    for (int j = 0; j < 4; j++)
        wv[j] = isI ? weights[kx + j] : 1.0f;

    int lnz = 0;
    #pragma unroll
    for (int n = 0; n < 8; n++) {
        float p[4];
        #pragma unroll
        for (int kp = 0; kp < 2; kp++) {
            ull d;
            FMA2(d, acc[n][kp], m1, nt3[kp]);  // -(acc) - t3
            float d0, d1; unpack2(d, d0, d1);
            p[2*kp]   = expf(d0) * wv[2*kp];
            p[2*kp+1] = expf(d1) * wv[2*kp+1];
            lnz |= (p[2*kp] != 0.0f) | (p[2*kp+1] != 0.0f);
        }
        *(float4*)(phi + (size_t)(n0 + ny + n) * KK + kx) =
            make_float4(p[0], p[1], p[2], p[3]);
    }
    int any = __syncthreads_or(lnz);
    if (t == 0) {
        g_nz[isI ? 0 : 1][2*blockIdx.x]     = any;
        g_nz[isI ? 0 : 1][2*blockIdx.x + 1] = any;
    }
}

// ---------------------------------------------------------------------------
// GEMM (R1-proven, unchanged): out[n,m] = sum_k phi_i[n,k]*phi_j[m,k].
// 64x64 tiles, 256 threads, 4x4 micro-tile. Zero tiles write zeros (exact).
// ---------------------------------------------------------------------------
__global__ __launch_bounds__(256)
void gemm_kernel(float* __restrict__ out) {
    const int bm = blockIdx.y;
    const int bn = blockIdx.x;
    const int t  = threadIdx.x;
    const int txm = (t & 15) * 4;
    const int tyn = (t >> 4) * 4;

    if (g_nz[0][bm] == 0 || g_nz[1][bn] == 0) {
        float4 z = make_float4(0.f, 0.f, 0.f, 0.f);
        #pragma unroll
        for (int i = 0; i < 4; i++) {
            size_t row = (size_t)(bm * 64 + tyn + i);
            *(float4*)(out + row * NN + bn * 64 + txm) = z;
        }
        return;
    }

    __shared__ float As[64][68];
    __shared__ float Bs[64][68];
    #pragma unroll
    for (int v = 0; v < 4; v++) {
        int vid = t + v * 256;
        int row = vid >> 4;
        int k4  = (vid & 15) * 4;
        float4 a = *(const float4*)(g_phi_i + (size_t)(bm * 64 + row) * KK + k4);
        As[k4+0][row] = a.x; As[k4+1][row] = a.y; As[k4+2][row] = a.z; As[k4+3][row] = a.w;
        float4 b = *(const float4*)(g_phi_j + (size_t)(bn * 64 + row) * KK + k4);
        Bs[k4+0][row] = b.x; Bs[k4+1][row] = b.y; Bs[k4+2][row] = b.z; Bs[k4+3][row] = b.w;
    }
    __syncthreads();

    float acc[4][4];
    #pragma unroll
    for (int i = 0; i < 4; i++)
        #pragma unroll
        for (int j = 0; j < 4; j++) acc[i][j] = 0.f;

    #pragma unroll 8
    for (int k = 0; k < 64; k++) {
        float4 a4 = *(const float4*)&As[k][tyn];
        float4 b4 = *(const float4*)&Bs[k][txm];
        float av[4] = {a4.x, a4.y, a4.z, a4.w};
        float bv[4] = {b4.x, b4.y, b4.z, b4.w};
        #pragma unroll
        for (int i = 0; i < 4; i++)
            #pragma unroll
            for (int j = 0; j < 4; j++)
                acc[i][j] = fmaf(av[i], bv[j], acc[i][j]);
    }

    #pragma unroll
    for (int i = 0; i < 4; i++) {
        size_t row = (size_t)(bm * 64 + tyn + i);
        *(float4*)(out + row * NN + bn * 64 + txm) =
            make_float4(acc[i][0], acc[i][1], acc[i][2], acc[i][3]);
    }
}

// ---------------------------------------------------------------------------
extern "C" void kernel_launch(void* const* d_in, const int* in_sizes, int n_in,
                              void* d_out, int out_size) {
    const float* f_i     = (const float*)d_in[0];
    const float* f_j     = (const float*)d_in[1];
    const float* means   = (const float*)d_in[2];
    const float* scales  = (const float*)d_in[3];
    const float* weights = (const float*)d_in[4];
    float* out = (float*)d_out;

    prep_kernel<<<KK, 512>>>(means, scales);
    phi_kernel<<<dim3(PHI_NBLK, 2), 256>>>(f_i, f_j, weights);
    gemm_kernel<<<dim3(NBLK, NBLK), 256>>>(out);
}